// round 2
// baseline (speedup 1.0000x reference)
#include <cuda_runtime.h>
#include <cuda_bf16.h>

// Scratch for the per-batch broadcast vector y[b, c] (B=8, C=256).
// __device__ global (allocation-free per harness rules).
__device__ float g_y[8 * 256];

#define CC 256
#define BB 8
#define PD 16

// One block per batch, 256 threads. Computes:
//   ctx  = param_tokens[b] @ Wparam + bparam           (256)
//   ln   = layernorm(ctx) * ctx_g + ctx_b              (256)
//   v    = ln @ Wkv[:, 256:512]                        (256)
//   y    = v @ Wout + bout                             (256)
__global__ __launch_bounds__(256) void compute_y_kernel(
    const float* __restrict__ param_tokens,  // (8,16)
    const float* __restrict__ Wparam,        // (16,256)
    const float* __restrict__ bparam,        // (256)
    const float* __restrict__ ctx_g,         // (256)
    const float* __restrict__ ctx_b,         // (256)
    const float* __restrict__ Wkv,           // (256,512)
    const float* __restrict__ Wout,          // (256,256)
    const float* __restrict__ bout)          // (256)
{
    const int b = blockIdx.x;
    const int t = threadIdx.x;  // 0..255

    __shared__ float s_ln[CC];
    __shared__ float s_v[CC];
    __shared__ float s_red[8];

    // ctx[t]
    float ctx = bparam[t];
#pragma unroll
    for (int p = 0; p < PD; p++)
        ctx = fmaf(param_tokens[b * PD + p], Wparam[p * CC + t], ctx);

    // mean over 256 (warp shuffle + cross-warp shared)
    float s = ctx;
#pragma unroll
    for (int o = 16; o > 0; o >>= 1) s += __shfl_xor_sync(0xffffffffu, s, o);
    if ((t & 31) == 0) s_red[t >> 5] = s;
    __syncthreads();
    float tot = 0.0f;
#pragma unroll
    for (int w = 0; w < 8; w++) tot += s_red[w];
    const float mean = tot * (1.0f / 256.0f);

    const float d = ctx - mean;
    __syncthreads();  // protect s_red reuse

    // variance
    float sq = d * d;
#pragma unroll
    for (int o = 16; o > 0; o >>= 1) sq += __shfl_xor_sync(0xffffffffu, sq, o);
    if ((t & 31) == 0) s_red[t >> 5] = sq;
    __syncthreads();
    float vtot = 0.0f;
#pragma unroll
    for (int w = 0; w < 8; w++) vtot += s_red[w];
    const float var = vtot * (1.0f / 256.0f);

    const float ln = d * rsqrtf(var + 1e-5f) * ctx_g[t] + ctx_b[t];
    s_ln[t] = ln;
    __syncthreads();

    // v[t] = sum_c ln[c] * Wkv[c, 256 + t]   (Wkv row stride = 512)
    float v = 0.0f;
#pragma unroll 8
    for (int c = 0; c < CC; c++)
        v = fmaf(s_ln[c], Wkv[c * 512 + 256 + t], v);
    s_v[t] = v;
    __syncthreads();

    // y[t] = sum_d v[d] * Wout[d, t] + bout[t]
    float y = bout[t];
#pragma unroll 8
    for (int dd = 0; dd < CC; dd++)
        y = fmaf(s_v[dd], Wout[dd * CC + t], y);

    g_y[b * CC + t] = y;
}

// out[b,n,c] = img[b,n,c] + y[b,c]
// Vectorized float4: 8*1024*256/4 = 524288 elements, one per thread.
__global__ __launch_bounds__(256) void add_broadcast_kernel(
    const float4* __restrict__ img, float4* __restrict__ out)
{
    const int i = blockIdx.x * blockDim.x + threadIdx.x;  // 0..524287
    // flat float index f = 4*i; b = f >> 18 = i >> 16; c4 = (f>>2) & 63 = i & 63
    const int b = i >> 16;
    const float4 yv = reinterpret_cast<const float4*>(g_y)[b * 64 + (i & 63)];
    float4 x = img[i];
    x.x += yv.x;
    x.y += yv.y;
    x.z += yv.z;
    x.w += yv.w;
    out[i] = x;
}

extern "C" void kernel_launch(void* const* d_in, const int* in_sizes, int n_in,
                              void* d_out, int out_size) {
    // metadata order:
    // 0 img_tokens (8,1024,256)   1 param_tokens (8,16)
    // 2 img_norm_g  3 img_norm_b  4 Wq (unused — cancels algebraically)
    // 5 Wparam (16,256)  6 bparam (256)
    // 7 ctx_norm_g (256) 8 ctx_norm_b (256)
    // 9 Wkv (256,512)   10 Wout (256,256)  11 bout (256)
    const float* img          = (const float*)d_in[0];
    const float* param_tokens = (const float*)d_in[1];
    const float* Wparam       = (const float*)d_in[5];
    const float* bparam       = (const float*)d_in[6];
    const float* ctx_g        = (const float*)d_in[7];
    const float* ctx_b        = (const float*)d_in[8];
    const float* Wkv          = (const float*)d_in[9];
    const float* Wout         = (const float*)d_in[10];
    const float* bout         = (const float*)d_in[11];

    compute_y_kernel<<<8, 256>>>(param_tokens, Wparam, bparam, ctx_g, ctx_b,
                                 Wkv, Wout, bout);
    add_broadcast_kernel<<<2048, 256>>>((const float4*)img, (float4*)d_out);
}

// round 4
// speedup vs baseline: 1.6617x; 1.6617x over previous
#include <cuda_runtime.h>
#include <cuda_bf16.h>

// Scratch for the per-batch broadcast vector y[b, c] (B=8, C=256).
__device__ float g_y[8 * 256];

#define CC 256
#define PD 16

// One block per batch, 1024 threads. Reductions split 4-ways to shorten the
// serial FMA chain (64 per thread instead of 256).
//   ctx  = param_tokens[b] @ Wparam + bparam           (256)
//   ln   = layernorm(ctx) * ctx_g + ctx_b              (256)
//   v    = ln @ Wkv[:, 256:512]                        (256)
//   y    = v @ Wout + bout                             (256)
__global__ __launch_bounds__(1024) void compute_y_kernel(
    const float* __restrict__ param_tokens,  // (8,16)
    const float* __restrict__ Wparam,        // (16,256)
    const float* __restrict__ bparam,        // (256)
    const float* __restrict__ ctx_g,         // (256)
    const float* __restrict__ ctx_b,         // (256)
    const float* __restrict__ Wkv,           // (256,512)
    const float* __restrict__ Wout,          // (256,256)
    const float* __restrict__ bout)          // (256)
{
    const int b   = blockIdx.x;
    const int t   = threadIdx.x;   // 0..1023
    const int col = t & 255;       // output column
    const int r   = t >> 8;        // 0..3 reduction slice
    const int wrp = t >> 5;        // 0..31
    const int lane = t & 31;

    __shared__ float s_ln[CC];
    __shared__ float s_v[CC];
    __shared__ float s_part[1024];
    __shared__ float s_red[32];

    // ctx[col] — computed redundantly by all 4 r-groups (cheap, avoids a sync)
    float ctx = bparam[col];
#pragma unroll
    for (int p = 0; p < PD; p++)
        ctx = fmaf(param_tokens[b * PD + p], Wparam[p * CC + col], ctx);

    // mean: warp shuffle; warps 0..7 (r=0 group) cover cols 0..255 exactly
    float s = ctx;
#pragma unroll
    for (int o = 16; o > 0; o >>= 1) s += __shfl_xor_sync(0xffffffffu, s, o);
    if (lane == 0) s_red[wrp] = s;
    __syncthreads();
    float tot = 0.0f;
#pragma unroll
    for (int w = 0; w < 8; w++) tot += s_red[w];
    const float mean = tot * (1.0f / 256.0f);
    const float d = ctx - mean;
    __syncthreads();  // protect s_red reuse

    // variance
    float sq = d * d;
#pragma unroll
    for (int o = 16; o > 0; o >>= 1) sq += __shfl_xor_sync(0xffffffffu, sq, o);
    if (lane == 0) s_red[wrp] = sq;
    __syncthreads();
    float vtot = 0.0f;
#pragma unroll
    for (int w = 0; w < 8; w++) vtot += s_red[w];
    const float var = vtot * (1.0f / 256.0f);

    const float ln = d * rsqrtf(var + 1e-5f) * ctx_g[col] + ctx_b[col];
    if (r == 0) s_ln[col] = ln;
    __syncthreads();

    // GEMV1: v[col] = sum_c ln[c] * Wkv[c, 256+col], slice c in [64r, 64r+64)
    {
        const float* __restrict__ Wk = Wkv + 256 + col;
        float v = 0.0f;
        const int c0 = r * 64;
#pragma unroll 16
        for (int c = c0; c < c0 + 64; c++)
            v = fmaf(s_ln[c], Wk[c * 512], v);
        s_part[t] = v;
    }
    __syncthreads();
    if (r == 0)
        s_v[col] = s_part[col] + s_part[col + 256] + s_part[col + 512] + s_part[col + 768];
    __syncthreads();

    // GEMV2: y[col] = sum_d v[d] * Wout[d, col] + bout[col]
    {
        float y = 0.0f;
        const int d0 = r * 64;
#pragma unroll 16
        for (int dd = d0; dd < d0 + 64; dd++)
            y = fmaf(s_v[dd], Wout[dd * CC + col], y);
        s_part[t] = y;
    }
    __syncthreads();
    if (r == 0)
        g_y[b * CC + col] = s_part[col] + s_part[col + 256] + s_part[col + 512]
                          + s_part[col + 768] + bout[col];
}

// out[b,n,c] = img[b,n,c] + y[b,c]
// 128 blocks (8 batches x 16 row-groups) x 256 threads, single wave.
// Each thread owns a fixed (b, c4) column: y loaded ONCE to register, then
// 16 independent LDG.128/STG.128 pairs (MLP=16).
__global__ __launch_bounds__(256) void add_broadcast_kernel(
    const float4* __restrict__ img, float4* __restrict__ out)
{
    const int b    = blockIdx.x >> 4;       // 0..7
    const int rg   = blockIdx.x & 15;       // row-group of 64 rows
    const int t    = threadIdx.x;
    const int c4   = t & 63;                // float4 column 0..63
    const int rsub = t >> 6;                // 0..3

    const float4 yv = reinterpret_cast<const float4*>(g_y)[b * 64 + c4];

    // float4 index of (b, row, c4) = b*65536 + row*64 + c4
    const int base = b * 65536 + (rg * 64 + rsub) * 64 + c4;
#pragma unroll
    for (int i = 0; i < 16; i++) {
        const int idx = base + i * 4 * 64;  // rows step by 4
        float4 x = img[idx];
        x.x += yv.x;
        x.y += yv.y;
        x.z += yv.z;
        x.w += yv.w;
        out[idx] = x;
    }
}

extern "C" void kernel_launch(void* const* d_in, const int* in_sizes, int n_in,
                              void* d_out, int out_size) {
    // 0 img_tokens (8,1024,256)   1 param_tokens (8,16)
    // 2 img_norm_g  3 img_norm_b  4 Wq (unused — cancels algebraically)
    // 5 Wparam (16,256)  6 bparam (256)
    // 7 ctx_norm_g (256) 8 ctx_norm_b (256)
    // 9 Wkv (256,512)   10 Wout (256,256)  11 bout (256)
    const float* img          = (const float*)d_in[0];
    const float* param_tokens = (const float*)d_in[1];
    const float* Wparam       = (const float*)d_in[5];
    const float* bparam       = (const float*)d_in[6];
    const float* ctx_g        = (const float*)d_in[7];
    const float* ctx_b        = (const float*)d_in[8];
    const float* Wkv          = (const float*)d_in[9];
    const float* Wout         = (const float*)d_in[10];
    const float* bout         = (const float*)d_in[11];

    compute_y_kernel<<<8, 1024>>>(param_tokens, Wparam, bparam, ctx_g, ctx_b,
                                  Wkv, Wout, bout);
    add_broadcast_kernel<<<128, 256>>>((const float4*)img, (float4*)d_out);
}